// round 12
// baseline (speedup 1.0000x reference)
#include <cuda_runtime.h>
#include <math.h>

#define BATCH 4096
#define NIN   512
#define NREP  512
#define NOUT  640
#define RW    512
#define RB    64
#define NNZ   16384

// Scratch (static device globals — allowed)
__device__ float g_t[RW];
__device__ float g_Wp[NOUT * NIN];
__device__ float g_bp[NOUT];
__device__ float g_lin[BATCH * NOUT];     // K-half 0 partial (+bias)
__device__ float g_lin2[BATCH * NOUT];    // K-half 1 partial
__device__ float g_pre[NOUT * BATCH];     // preact, TRANSPOSED [ch][batch]
__device__ uint2 g_pair[NNZ];             // (src*33 | col*33<<16, bits(param))
__device__ int   g_row_start[NOUT + 1];

// ---------------------------------------------------------------------------
// K0: zero g_t (also keeps k3 at launch slot 4 -> ncu profiles it)
// ---------------------------------------------------------------------------
__global__ void kz(void) { g_t[threadIdx.x] = 0.0f; }

// ---------------------------------------------------------------------------
// K1: t = Qw^T @ wflat   (measured at DRAM roofline — FROZEN)
// ---------------------------------------------------------------------------
__global__ __launch_bounds__(512) void k1_qwt(const float* __restrict__ Qw,
                                              const float* __restrict__ w) {
    __shared__ float s_w[256];
    const int tid = threadIdx.x;
    const int rowBase = blockIdx.x * 256;
    if (tid < 256) s_w[tid] = w[rowBase + tid];
    __syncthreads();

    float acc = 0.0f;
    const float* p = Qw + (size_t)rowBase * RW + tid;
#pragma unroll 8
    for (int i = 0; i < 256; i++) {
        acc += p[(size_t)i * RW] * s_w[i];
    }
    atomicAdd(&g_t[tid], acc);
}

// ---------------------------------------------------------------------------
// K2: Wp[i] = dot(Qw[i,:], t)  (second Qw stream — at roofline, FROZEN)
// Blocks 0..2559: GEMV. Block 2560: CSR sort. Block 2561: bias.
// ---------------------------------------------------------------------------
__global__ __launch_bounds__(256) void k2_wp(
    const float* __restrict__ Qw,
    const int* __restrict__ bsrc, const int* __restrict__ brow,
    const int* __restrict__ bcol, const float* __restrict__ bp_params,
    const float* __restrict__ Qb, const float* __restrict__ b) {
    const int tid = threadIdx.x;

    if (blockIdx.x >= 2560) {
        if (blockIdx.x == 2560) {
            __shared__ int c[NOUT];
            __shared__ int scan[NOUT];
            __shared__ int off[NOUT];
            for (int i = tid; i < NOUT; i += 256) c[i] = 0;
            __syncthreads();
            for (int k = tid; k < NNZ; k += 256) atomicAdd(&c[brow[k]], 1);
            __syncthreads();
            if (tid < 32) {
                int base = 0;
#pragma unroll
                for (int ch = 0; ch < NOUT / 32; ch++) {
                    int v = c[ch * 32 + tid];
#pragma unroll
                    for (int d = 1; d < 32; d <<= 1) {
                        int n = __shfl_up_sync(0xffffffffu, v, d);
                        if (tid >= d) v += n;
                    }
                    scan[ch * 32 + tid] = v + base;
                    base += __shfl_sync(0xffffffffu, v, 31);
                }
            }
            __syncthreads();
            for (int i = tid; i < NOUT; i += 256) {
                const int s = scan[i] - c[i];
                g_row_start[i] = s;
                off[i] = s;
            }
            if (tid == 0) g_row_start[NOUT] = NNZ;
            __syncthreads();
            for (int k = tid; k < NNZ; k += 256) {
                const int r = brow[k];
                const int pos = atomicAdd(&off[r], 1);
                // pre-multiplied smem indices: src*33 | (col*33)<<16
                g_pair[pos] = make_uint2(
                    (unsigned)(bsrc[k] * 33) | ((unsigned)(bcol[k] * 33) << 16),
                    __float_as_uint(bp_params[k]));
            }
        } else {
            __shared__ float s_part[4][RB];
            __shared__ float s_s[RB];
            const int r = tid & 63;
            const int chunk = tid >> 6;
            float acc = 0.0f;
            for (int i = chunk * 160; i < chunk * 160 + 160; i++)
                acc += Qb[i * RB + r] * b[i];
            s_part[chunk][r] = acc;
            __syncthreads();
            if (tid < RB) {
                s_s[tid] = s_part[0][tid] + s_part[1][tid] +
                           s_part[2][tid] + s_part[3][tid];
            }
            __syncthreads();
            for (int j = tid; j < NOUT; j += 256) {
                const float4* q4 = reinterpret_cast<const float4*>(Qb + j * RB);
                const float4* s4 = reinterpret_cast<const float4*>(s_s);
                float a = 0.0f;
#pragma unroll
                for (int u = 0; u < 16; u++) {
                    float4 q = q4[u];
                    float4 s = s4[u];
                    a += q.x * s.x + q.y * s.y + q.z * s.z + q.w * s.w;
                }
                g_bp[j] = a;
            }
        }
        return;
    }

    __shared__ float s_t[RW];
    for (int i = tid; i < RW; i += 256) s_t[i] = g_t[i];
    __syncthreads();

    const int warp = tid >> 5;
    const int lane = tid & 31;
    const int row0 = (blockIdx.x * 8 + warp) * 16;
    const float4* t4 = reinterpret_cast<const float4*>(s_t);

    for (int rr = 0; rr < 16; rr++) {
        const int row = row0 + rr;
        const float4* p4 = reinterpret_cast<const float4*>(Qw + (size_t)row * RW);
        float acc = 0.0f;
#pragma unroll
        for (int u = 0; u < 4; u++) {
            float4 q = p4[lane + 32 * u];
            float4 tt = t4[lane + 32 * u];
            acc += q.x * tt.x + q.y * tt.y + q.z * tt.z + q.w * tt.w;
        }
#pragma unroll
        for (int off = 16; off > 0; off >>= 1)
            acc += __shfl_xor_sync(0xffffffffu, acc, off);
        if (lane == 0) g_Wp[row] = acc;
    }
}

// ---------------------------------------------------------------------------
// K3: lin = x @ Wp^T + bp, SPLIT-K x2  (4096x512 @ 512x640)
// BM=64, BN=128, BK=16, 256 threads, 4x8 per-thread f32x2 tile (1 B/FMA).
// acc = 32 u64 regs -> ~80 regs/thread -> ~6 resident blocks/SM (~34 warps).
// grid (5, 64, 2) = 640 blocks. LAUNCH #4 -> profiled.
// ---------------------------------------------------------------------------
__global__ __launch_bounds__(256) void k3_gemm(const float* __restrict__ x) {
    __shared__ float As[16][68];
    __shared__ float Bs[16][132];

    const int tid = threadIdx.x;
    const int tx = tid & 15;      // cols {tx*4..+3} and {64+tx*4..+3}
    const int ty = tid >> 4;      // rows ty*4 .. +3  (16 groups x 4 = 64)
    const int bn0 = blockIdx.x * 128;
    const int bm0 = blockIdx.y * 64;
    const int kb  = blockIdx.z * 256;     // K half base

    // A loader: 64 rows x 16 k = 256 float4, 1/thread
    const int am = tid >> 2, af = tid & 3;
    const float* apg = x + (size_t)(bm0 + am) * NIN + kb + af * 4;
    // B loader: 128 rows x 16 k = 512 float4, 2/thread
    int bn_[2], bf_[2];
    const float* bpg[2];
#pragma unroll
    for (int i = 0; i < 2; i++) {
        const int idx = tid + 256 * i;
        bn_[i] = idx >> 2;
        bf_[i] = idx & 3;
        bpg[i] = g_Wp + (size_t)(bn0 + bn_[i]) * NIN + kb + bf_[i] * 4;
    }

    unsigned long long acc[4][4];
#pragma unroll
    for (int i = 0; i < 4; i++)
#pragma unroll
        for (int j = 0; j < 4; j++) acc[i][j] = 0ull;

    float4 ar = *reinterpret_cast<const float4*>(apg);
    float4 br0 = *reinterpret_cast<const float4*>(bpg[0]);
    float4 br1 = *reinterpret_cast<const float4*>(bpg[1]);

    for (int kt = 0; kt < 16; kt++) {
        As[af * 4 + 0][am] = ar.x; As[af * 4 + 1][am] = ar.y;
        As[af * 4 + 2][am] = ar.z; As[af * 4 + 3][am] = ar.w;
        Bs[bf_[0] * 4 + 0][bn_[0]] = br0.x;
        Bs[bf_[0] * 4 + 1][bn_[0]] = br0.y;
        Bs[bf_[0] * 4 + 2][bn_[0]] = br0.z;
        Bs[bf_[0] * 4 + 3][bn_[0]] = br0.w;
        Bs[bf_[1] * 4 + 0][bn_[1]] = br1.x;
        Bs[bf_[1] * 4 + 1][bn_[1]] = br1.y;
        Bs[bf_[1] * 4 + 2][bn_[1]] = br1.z;
        Bs[bf_[1] * 4 + 3][bn_[1]] = br1.w;
        __syncthreads();
        if (kt < 15) {
            ar  = *reinterpret_cast<const float4*>(apg    + (kt + 1) * 16);
            br0 = *reinterpret_cast<const float4*>(bpg[0] + (kt + 1) * 16);
            br1 = *reinterpret_cast<const float4*>(bpg[1] + (kt + 1) * 16);
        }
#pragma unroll
        for (int kk = 0; kk < 16; kk++) {
            const float4 a0 = *reinterpret_cast<const float4*>(&As[kk][ty * 4]);
            const ulonglong2 bL =
                *reinterpret_cast<const ulonglong2*>(&Bs[kk][tx * 4]);
            const ulonglong2 bH =
                *reinterpret_cast<const ulonglong2*>(&Bs[kk][64 + tx * 4]);
            unsigned long long a2[4];
            asm("mov.b64 %0, {%1, %1};" : "=l"(a2[0]) : "f"(a0.x));
            asm("mov.b64 %0, {%1, %1};" : "=l"(a2[1]) : "f"(a0.y));
            asm("mov.b64 %0, {%1, %1};" : "=l"(a2[2]) : "f"(a0.z));
            asm("mov.b64 %0, {%1, %1};" : "=l"(a2[3]) : "f"(a0.w));
#pragma unroll
            for (int i = 0; i < 4; i++) {
                asm("fma.rn.f32x2 %0, %1, %2, %0;" : "+l"(acc[i][0]) : "l"(a2[i]), "l"(bL.x));
                asm("fma.rn.f32x2 %0, %1, %2, %0;" : "+l"(acc[i][1]) : "l"(a2[i]), "l"(bL.y));
                asm("fma.rn.f32x2 %0, %1, %2, %0;" : "+l"(acc[i][2]) : "l"(a2[i]), "l"(bH.x));
                asm("fma.rn.f32x2 %0, %1, %2, %0;" : "+l"(acc[i][3]) : "l"(a2[i]), "l"(bH.y));
            }
        }
        __syncthreads();
    }

    // epilogue: z=0 adds bias -> g_lin; z=1 raw partial -> g_lin2
    float* gout = (blockIdx.z == 0) ? g_lin : g_lin2;
    float4 bv0 = make_float4(0.f, 0.f, 0.f, 0.f);
    float4 bv1 = make_float4(0.f, 0.f, 0.f, 0.f);
    if (blockIdx.z == 0) {
        bv0 = *reinterpret_cast<const float4*>(&g_bp[bn0 + tx * 4]);
        bv1 = *reinterpret_cast<const float4*>(&g_bp[bn0 + 64 + tx * 4]);
    }
#pragma unroll
    for (int i = 0; i < 4; i++) {
        const int row = bm0 + ty * 4 + i;
        float r0, r1, r2, r3, r4, r5, r6, r7;
        asm("mov.b64 {%0, %1}, %2;" : "=f"(r0), "=f"(r1) : "l"(acc[i][0]));
        asm("mov.b64 {%0, %1}, %2;" : "=f"(r2), "=f"(r3) : "l"(acc[i][1]));
        asm("mov.b64 {%0, %1}, %2;" : "=f"(r4), "=f"(r5) : "l"(acc[i][2]));
        asm("mov.b64 {%0, %1}, %2;" : "=f"(r6), "=f"(r7) : "l"(acc[i][3]));
        float* dst = gout + (size_t)row * NOUT + bn0;
        *reinterpret_cast<float4*>(dst + tx * 4) =
            make_float4(r0 + bv0.x, r1 + bv0.y, r2 + bv0.z, r3 + bv0.w);
        *reinterpret_cast<float4*>(dst + 64 + tx * 4) =
            make_float4(r4 + bv1.x, r5 + bv1.y, r6 + bv1.z, r7 + bv1.w);
    }
}

// ---------------------------------------------------------------------------
// K4a: bilinear CSR -> preact; prefetched pair quads (hide L2 latency),
// pre-multiplied smem indices (src*33 / col*33 packed by k_sort).
// ---------------------------------------------------------------------------
#define K4_P 33
extern __shared__ float2 k4_s2[];   // [640][33]

__global__ __launch_bounds__(512) void k4a_bilinear(void) {
    const int tid  = threadIdx.x;
    const int warp = tid >> 5;
    const int lane = tid & 31;
    const int grp  = blockIdx.x >> 1;
    const int half = blockIdx.x & 1;
    const int b0   = grp * 64;

#pragma unroll
    for (int i = 0; i < 4; i++) {
        const int bb = warp + 16 * i;
        const float* src1 = g_lin  + (size_t)(b0 + bb) * NOUT;
        const float* src2 = g_lin2 + (size_t)(b0 + bb) * NOUT;
        float* base = reinterpret_cast<float*>(k4_s2) + (bb & 1);
        const int pr = bb >> 1;
        for (int ch = lane; ch < NOUT; ch += 32)
            base[(ch * K4_P + pr) * 2] = src1[ch] + src2[ch];
    }
    __syncthreads();

    const unsigned long long* s_u64 =
        reinterpret_cast<const unsigned long long*>(k4_s2) + lane;
    unsigned long long c01;
    asm("mov.b64 %0, {%1, %1};" : "=l"(c01) : "f"(0.1f));

#define K4_STEP(ACC, PR)                                                      \
    {                                                                         \
        unsigned long long av = s_u64[(PR).x & 0xFFFFu];                      \
        unsigned long long bv = s_u64[(PR).x >> 16];                          \
        const float pf = __uint_as_float((PR).y);                             \
        unsigned long long pp, t;                                             \
        asm("mov.b64 %0, {%1, %1};" : "=l"(pp) : "f"(pf));                    \
        asm("mul.rn.f32x2 %0, %1, %2;" : "=l"(t) : "l"(av), "l"(bv));         \
        asm("fma.rn.f32x2 %0, %1, %2, %0;" : "+l"(ACC) : "l"(t), "l"(pp));    \
    }

    for (int i = 0; i < 20; i++) {
        const int row = half * 320 + warp + 16 * i;
        const int ks = g_row_start[row];
        const int ke = g_row_start[row + 1];
        unsigned long long a0 = 0ull, a1 = 0ull, a2c = 0ull, a3 = 0ull;
        int k = ks;
        uint2 q0, q1, q2, q3;
        if (k + 3 < ke) {
            q0 = g_pair[k]; q1 = g_pair[k + 1];
            q2 = g_pair[k + 2]; q3 = g_pair[k + 3];
            // pipelined main loop: prefetch next quad before consuming current
            for (; k + 7 < ke; k += 4) {
                const uint2 n0 = g_pair[k + 4];
                const uint2 n1 = g_pair[k + 5];
                const uint2 n2 = g_pair[k + 6];
                const uint2 n3 = g_pair[k + 7];
                K4_STEP(a0, q0)
                K4_STEP(a1, q1)
                K4_STEP(a2c, q2)
                K4_STEP(a3, q3)
                q0 = n0; q1 = n1; q2 = n2; q3 = n3;
            }
            K4_STEP(a0, q0)
            K4_STEP(a1, q1)
            K4_STEP(a2c, q2)
            K4_STEP(a3, q3)
            k += 4;
        }
        for (; k < ke; k++) {
            const uint2 p0 = g_pair[k];
            K4_STEP(a0, p0)
        }
        unsigned long long acc;
        asm("add.rn.f32x2 %0, %1, %2;" : "=l"(acc) : "l"(a0), "l"(a1));
        asm("add.rn.f32x2 %0, %1, %2;" : "+l"(acc) : "l"(acc), "l"(a2c));
        asm("add.rn.f32x2 %0, %1, %2;" : "+l"(acc) : "l"(acc), "l"(a3));

        unsigned long long linv = s_u64[row * K4_P];
        unsigned long long pv;
        asm("mul.rn.f32x2 %0, %1, %2;" : "=l"(pv) : "l"(acc), "l"(c01));
        asm("add.rn.f32x2 %0, %1, %2;" : "+l"(pv) : "l"(pv), "l"(linv));
        *reinterpret_cast<unsigned long long*>(
            g_pre + (size_t)row * BATCH + b0 + 2 * lane) = pv;
    }
}

// ---------------------------------------------------------------------------
// K4b: gated nonlinearity from transposed preact (FROZEN, ~6us)
// ---------------------------------------------------------------------------
__global__ __launch_bounds__(256) void k4b_gate(
    const int* __restrict__ gate_idx, float* __restrict__ out) {
    __shared__ float s_t[32][257];
    const int tid = threadIdx.x;
    const int b0 = blockIdx.x * 256;
    const int j0 = blockIdx.y * 32;

#pragma unroll 4
    for (int jj = 0; jj < 32; jj++) {
        const int j = j0 + jj;
        const int gi = gate_idx[j];
        const float v = g_pre[(size_t)j * BATCH + b0 + tid];
        const float g = g_pre[(size_t)gi * BATCH + b0 + tid];
        s_t[jj][tid] = v / (1.0f + __expf(-g));
    }
    __syncthreads();

    float* dst = out + (size_t)(b0 + tid) * NREP + j0;
#pragma unroll
    for (int q = 0; q < 8; q++) {
        float4 v = make_float4(s_t[q * 4 + 0][tid], s_t[q * 4 + 1][tid],
                               s_t[q * 4 + 2][tid], s_t[q * 4 + 3][tid]);
        *reinterpret_cast<float4*>(dst + q * 4) = v;
    }
}

// ---------------------------------------------------------------------------
// Launch
// ---------------------------------------------------------------------------
extern "C" void kernel_launch(void* const* d_in, const int* in_sizes, int n_in,
                              void* d_out, int out_size) {
    const float* x        = (const float*)d_in[0];
    const float* W_weight = (const float*)d_in[1];
    const float* b        = (const float*)d_in[2];
    const float* Qw       = (const float*)d_in[3];
    const float* Qb       = (const float*)d_in[4];
    const float* bi_p     = (const float*)d_in[5];
    const int*   bi_src   = (const int*)d_in[6];
    const int*   bi_row   = (const int*)d_in[7];
    const int*   bi_col   = (const int*)d_in[8];
    const int*   gate_idx = (const int*)d_in[9];
    float* out = (float*)d_out;

    static int smem_set = 0;
    const int k4_smem_bytes = NOUT * K4_P * sizeof(float2);  // 168,960
    if (!smem_set) {
        cudaFuncSetAttribute(k4a_bilinear,
                             cudaFuncAttributeMaxDynamicSharedMemorySize,
                             k4_smem_bytes);
        smem_set = 1;
    }

    kz<<<1, 512>>>();
    k1_qwt<<<1280, 512>>>(Qw, W_weight);
    k2_wp<<<2562, 256>>>(Qw, bi_src, bi_row, bi_col, bi_p, Qb, b);
    k3_gemm<<<dim3(NOUT / 128, BATCH / 64, 2), 256>>>(x);  // launch #4 -> profiled
    k4a_bilinear<<<128, 512, k4_smem_bytes>>>();
    k4b_gate<<<dim3(BATCH / 256, NREP / 32), 256>>>(gate_idx, out);
}

// round 13
// speedup vs baseline: 1.0466x; 1.0466x over previous
#include <cuda_runtime.h>
#include <cuda_bf16.h>
#include <math.h>

#define BATCH 4096
#define NIN   512
#define NREP  512
#define NOUT  640
#define RW    512
#define RB    64
#define NNZ   16384

// Scratch (static device globals — allowed)
__device__ float g_t[RW];
__device__ float g_bp[NOUT];
__device__ float g_lin[BATCH * NOUT];            // lin (+bias)
__device__ float g_pre[NOUT * BATCH];            // preact, TRANSPOSED [ch][batch]
__device__ uint2 g_pair[NNZ];                    // (src | col<<10, bits(param))
__device__ int   g_row_start[NOUT + 1];
__device__ __nv_bfloat16 g_xh[BATCH * NIN];      // x hi/lo split
__device__ __nv_bfloat16 g_xl[BATCH * NIN];
__device__ __nv_bfloat16 g_Wph[NOUT * NIN];      // Wp hi/lo split
__device__ __nv_bfloat16 g_Wpl[NOUT * NIN];

// ---------------------------------------------------------------------------
// K0: zero g_t (also keeps k3 at launch slot 4 -> ncu profiles it)
// ---------------------------------------------------------------------------
__global__ void kz(void) { g_t[threadIdx.x] = 0.0f; }

// ---------------------------------------------------------------------------
// K1: t = Qw^T @ wflat (blocks 0..1279, at DRAM roofline — FROZEN)
// Blocks 1280..1311: x -> bf16 hi/lo split (rides free under the Qw stream).
// ---------------------------------------------------------------------------
__global__ __launch_bounds__(512) void k1_qwt(const float* __restrict__ Qw,
                                              const float* __restrict__ w,
                                              const float* __restrict__ x) {
    const int tid = threadIdx.x;
    if (blockIdx.x >= 1280) {
        const int cb = blockIdx.x - 1280;                 // 0..31
        const float4* x4 = reinterpret_cast<const float4*>(x);
        uint2* xh2 = reinterpret_cast<uint2*>(g_xh);
        uint2* xl2 = reinterpret_cast<uint2*>(g_xl);
#pragma unroll 4
        for (int i = 0; i < 32; i++) {
            const int idx4 = cb * 16384 + i * 512 + tid;  // float4 index
            const float4 v = x4[idx4];
            __nv_bfloat16 h0 = __float2bfloat16_rn(v.x);
            __nv_bfloat16 h1 = __float2bfloat16_rn(v.y);
            __nv_bfloat16 h2 = __float2bfloat16_rn(v.z);
            __nv_bfloat16 h3 = __float2bfloat16_rn(v.w);
            __nv_bfloat16 l0 = __float2bfloat16_rn(v.x - __bfloat162float(h0));
            __nv_bfloat16 l1 = __float2bfloat16_rn(v.y - __bfloat162float(h1));
            __nv_bfloat16 l2 = __float2bfloat16_rn(v.z - __bfloat162float(h2));
            __nv_bfloat16 l3 = __float2bfloat16_rn(v.w - __bfloat162float(h3));
            uint2 uh, ul;
            uh.x = ((unsigned)__bfloat16_as_ushort(h1) << 16) | __bfloat16_as_ushort(h0);
            uh.y = ((unsigned)__bfloat16_as_ushort(h3) << 16) | __bfloat16_as_ushort(h2);
            ul.x = ((unsigned)__bfloat16_as_ushort(l1) << 16) | __bfloat16_as_ushort(l0);
            ul.y = ((unsigned)__bfloat16_as_ushort(l3) << 16) | __bfloat16_as_ushort(l2);
            xh2[idx4] = uh;
            xl2[idx4] = ul;
        }
        return;
    }

    __shared__ float s_w[256];
    const int rowBase = blockIdx.x * 256;
    if (tid < 256) s_w[tid] = w[rowBase + tid];
    __syncthreads();

    float acc = 0.0f;
    const float* p = Qw + (size_t)rowBase * RW + tid;
#pragma unroll 8
    for (int i = 0; i < 256; i++) {
        acc += p[(size_t)i * RW] * s_w[i];
    }
    atomicAdd(&g_t[tid], acc);
}

// ---------------------------------------------------------------------------
// K2: Wp[i] = dot(Qw[i,:], t), written as bf16 hi/lo (second Qw stream).
// Blocks 0..2559: GEMV. Block 2560: CSR sort. Block 2561: bias.
// ---------------------------------------------------------------------------
__global__ __launch_bounds__(256) void k2_wp(
    const float* __restrict__ Qw,
    const int* __restrict__ bsrc, const int* __restrict__ brow,
    const int* __restrict__ bcol, const float* __restrict__ bp_params,
    const float* __restrict__ Qb, const float* __restrict__ b) {
    const int tid = threadIdx.x;

    if (blockIdx.x >= 2560) {
        if (blockIdx.x == 2560) {
            __shared__ int c[NOUT];
            __shared__ int scan[NOUT];
            __shared__ int off[NOUT];
            for (int i = tid; i < NOUT; i += 256) c[i] = 0;
            __syncthreads();
            for (int k = tid; k < NNZ; k += 256) atomicAdd(&c[brow[k]], 1);
            __syncthreads();
            if (tid < 32) {
                int base = 0;
#pragma unroll
                for (int ch = 0; ch < NOUT / 32; ch++) {
                    int v = c[ch * 32 + tid];
#pragma unroll
                    for (int d = 1; d < 32; d <<= 1) {
                        int n = __shfl_up_sync(0xffffffffu, v, d);
                        if (tid >= d) v += n;
                    }
                    scan[ch * 32 + tid] = v + base;
                    base += __shfl_sync(0xffffffffu, v, 31);
                }
            }
            __syncthreads();
            for (int i = tid; i < NOUT; i += 256) {
                const int s = scan[i] - c[i];
                g_row_start[i] = s;
                off[i] = s;
            }
            if (tid == 0) g_row_start[NOUT] = NNZ;
            __syncthreads();
            for (int k = tid; k < NNZ; k += 256) {
                const int r = brow[k];
                const int pos = atomicAdd(&off[r], 1);
                g_pair[pos] = make_uint2(
                    (unsigned)bsrc[k] | ((unsigned)bcol[k] << 10),
                    __float_as_uint(bp_params[k]));
            }
        } else {
            __shared__ float s_part[4][RB];
            __shared__ float s_s[RB];
            const int r = tid & 63;
            const int chunk = tid >> 6;
            float acc = 0.0f;
            for (int i = chunk * 160; i < chunk * 160 + 160; i++)
                acc += Qb[i * RB + r] * b[i];
            s_part[chunk][r] = acc;
            __syncthreads();
            if (tid < RB) {
                s_s[tid] = s_part[0][tid] + s_part[1][tid] +
                           s_part[2][tid] + s_part[3][tid];
            }
            __syncthreads();
            for (int j = tid; j < NOUT; j += 256) {
                const float4* q4 = reinterpret_cast<const float4*>(Qb + j * RB);
                const float4* s4 = reinterpret_cast<const float4*>(s_s);
                float a = 0.0f;
#pragma unroll
                for (int u = 0; u < 16; u++) {
                    float4 q = q4[u];
                    float4 s = s4[u];
                    a += q.x * s.x + q.y * s.y + q.z * s.z + q.w * s.w;
                }
                g_bp[j] = a;
            }
        }
        return;
    }

    __shared__ float s_t[RW];
    for (int i = tid; i < RW; i += 256) s_t[i] = g_t[i];
    __syncthreads();

    const int warp = tid >> 5;
    const int lane = tid & 31;
    const int row0 = (blockIdx.x * 8 + warp) * 16;
    const float4* t4 = reinterpret_cast<const float4*>(s_t);

    for (int rr = 0; rr < 16; rr++) {
        const int row = row0 + rr;
        const float4* p4 = reinterpret_cast<const float4*>(Qw + (size_t)row * RW);
        float acc = 0.0f;
#pragma unroll
        for (int u = 0; u < 4; u++) {
            float4 q = p4[lane + 32 * u];
            float4 tt = t4[lane + 32 * u];
            acc += q.x * tt.x + q.y * tt.y + q.z * tt.z + q.w * tt.w;
        }
#pragma unroll
        for (int off = 16; off > 0; off >>= 1)
            acc += __shfl_xor_sync(0xffffffffu, acc, off);
        if (lane == 0) {
            const __nv_bfloat16 hb = __float2bfloat16_rn(acc);
            g_Wph[row] = hb;
            g_Wpl[row] = __float2bfloat16_rn(acc - __bfloat162float(hb));
        }
    }
}

// ---------------------------------------------------------------------------
// K3: lin = x @ Wp^T + bp via bf16 3-way-split tensor-core mma.
// mma.sync.m16n8k16.row.col.f32.bf16: lin += xh*Wh + xh*Wl + xl*Wh.
// Block 256 thr = 8 warps (4m x 2n); block tile 128x64; warp tile 32x32.
// smem: [row][kpair] u32 tiles, stride 18 (16 pairs + 2 pad).
// grid (10, 32) = 320 blocks. LAUNCH #4 -> profiled.
// ---------------------------------------------------------------------------
#define KP 18   // u32 words per smem row

__device__ __forceinline__ void mma_bf16(float* d, const unsigned* a,
                                         const unsigned* bq) {
    asm volatile(
        "mma.sync.aligned.m16n8k16.row.col.f32.bf16.bf16.f32 "
        "{%0,%1,%2,%3}, {%4,%5,%6,%7}, {%8,%9}, {%0,%1,%2,%3};"
        : "+f"(d[0]), "+f"(d[1]), "+f"(d[2]), "+f"(d[3])
        : "r"(a[0]), "r"(a[1]), "r"(a[2]), "r"(a[3]), "r"(bq[0]), "r"(bq[1]));
}

__global__ __launch_bounds__(256) void k3_mma(void) {
    __shared__ unsigned Ah[128][KP];
    __shared__ unsigned Al[128][KP];
    __shared__ unsigned Bh[64][KP];
    __shared__ unsigned Bl[64][KP];

    const int tid  = threadIdx.x;
    const int warp = tid >> 5;
    const int lane = tid & 31;
    const int grp  = lane >> 2;
    const int tg   = lane & 3;
    const int wm = (warp >> 1) * 32;      // warp m offset within 128
    const int wn = (warp & 1) * 32;       // warp n offset within 64
    const int bn0 = blockIdx.x * 64;
    const int bm0 = blockIdx.y * 128;

    float d[2][4][4];
#pragma unroll
    for (int mf = 0; mf < 2; mf++)
#pragma unroll
        for (int nf = 0; nf < 4; nf++)
#pragma unroll
            for (int q = 0; q < 4; q++) d[mf][nf][q] = 0.0f;

    // loader indices (A: 2 uint4/thread, B: 1 uint4/thread per precision)
    const int arow0 = tid >> 1, aseg0 = (tid & 1) * 2;   // segs 0,1 or 2,3... wait
    // A tile: 128 rows x 4 segs (16B each) = 512 uint4 per precision.
    // thread handles idx = tid and tid+256: row = idx>>2, seg = idx&3.
    const int brow = tid >> 2, bseg = tid & 3;           // B: 64 rows x 4 segs

    for (int kt = 0; kt < 16; kt++) {
        const int kbase = kt * 32;   // bf16 elements
        // ---- load A (xh, xl) ----
#pragma unroll
        for (int i = 0; i < 2; i++) {
            const int idx = tid + 256 * i;
            const int row = idx >> 2;
            const int seg = idx & 3;
            const uint4 vh = *reinterpret_cast<const uint4*>(
                g_xh + (size_t)(bm0 + row) * NIN + kbase + seg * 8);
            const uint4 vl = *reinterpret_cast<const uint4*>(
                g_xl + (size_t)(bm0 + row) * NIN + kbase + seg * 8);
            Ah[row][seg * 4 + 0] = vh.x; Ah[row][seg * 4 + 1] = vh.y;
            Ah[row][seg * 4 + 2] = vh.z; Ah[row][seg * 4 + 3] = vh.w;
            Al[row][seg * 4 + 0] = vl.x; Al[row][seg * 4 + 1] = vl.y;
            Al[row][seg * 4 + 2] = vl.z; Al[row][seg * 4 + 3] = vl.w;
        }
        // ---- load B (Wph, Wpl) ----
        {
            const uint4 vh = *reinterpret_cast<const uint4*>(
                g_Wph + (size_t)(bn0 + brow) * NIN + kbase + bseg * 8);
            const uint4 vl = *reinterpret_cast<const uint4*>(
                g_Wpl + (size_t)(bn0 + brow) * NIN + kbase + bseg * 8);
            Bh[brow][bseg * 4 + 0] = vh.x; Bh[brow][bseg * 4 + 1] = vh.y;
            Bh[brow][bseg * 4 + 2] = vh.z; Bh[brow][bseg * 4 + 3] = vh.w;
            Bl[brow][bseg * 4 + 0] = vl.x; Bl[brow][bseg * 4 + 1] = vl.y;
            Bl[brow][bseg * 4 + 2] = vl.z; Bl[brow][bseg * 4 + 3] = vl.w;
        }
        __syncthreads();

#pragma unroll
        for (int s = 0; s < 2; s++) {
            const int kpb = s * 8;
            unsigned ah[2][4], al[2][4], bh[4][2], bl[4][2];
#pragma unroll
            for (int mf = 0; mf < 2; mf++) {
                const int r0 = wm + mf * 16 + grp;
                ah[mf][0] = Ah[r0][kpb + tg];
                ah[mf][1] = Ah[r0 + 8][kpb + tg];
                ah[mf][2] = Ah[r0][kpb + tg + 4];
                ah[mf][3] = Ah[r0 + 8][kpb + tg + 4];
                al[mf][0] = Al[r0][kpb + tg];
                al[mf][1] = Al[r0 + 8][kpb + tg];
                al[mf][2] = Al[r0][kpb + tg + 4];
                al[mf][3] = Al[r0 + 8][kpb + tg + 4];
            }
#pragma unroll
            for (int nf = 0; nf < 4; nf++) {
                const int n = wn + nf * 8 + grp;
                bh[nf][0] = Bh[n][kpb + tg];
                bh[nf][1] = Bh[n][kpb + tg + 4];
                bl[nf][0] = Bl[n][kpb + tg];
                bl[nf][1] = Bl[n][kpb + tg + 4];
            }
#pragma unroll
            for (int mf = 0; mf < 2; mf++)
#pragma unroll
                for (int nf = 0; nf < 4; nf++) {
                    mma_bf16(d[mf][nf], ah[mf], bh[nf]);
                    mma_bf16(d[mf][nf], ah[mf], bl[nf]);
                    mma_bf16(d[mf][nf], al[mf], bh[nf]);
                }
        }
        __syncthreads();
    }

    // epilogue: add bias, store float2 per fragment half
#pragma unroll
    for (int nf = 0; nf < 4; nf++) {
        const int col = bn0 + wn + nf * 8 + tg * 2;
        const float2 bv = *reinterpret_cast<const float2*>(&g_bp[col]);
#pragma unroll
        for (int mf = 0; mf < 2; mf++) {
            const int row0 = bm0 + wm + mf * 16 + grp;
            float2 v0 = make_float2(d[mf][nf][0] + bv.x, d[mf][nf][1] + bv.y);
            float2 v1 = make_float2(d[mf][nf][2] + bv.x, d[mf][nf][3] + bv.y);
            *reinterpret_cast<float2*>(g_lin + (size_t)row0 * NOUT + col) = v0;
            *reinterpret_cast<float2*>(g_lin + (size_t)(row0 + 8) * NOUT + col) = v1;
        }
    }
}

// ---------------------------------------------------------------------------
// K4a: bilinear CSR -> preact (round-11 form, single g_lin source)
// ---------------------------------------------------------------------------
#define K4_P 33
extern __shared__ float2 k4_s2[];   // [640][33]

__global__ __launch_bounds__(512) void k4a_bilinear(void) {
    const int tid  = threadIdx.x;
    const int warp = tid >> 5;
    const int lane = tid & 31;
    const int grp  = blockIdx.x >> 1;
    const int half = blockIdx.x & 1;
    const int b0   = grp * 64;

#pragma unroll
    for (int i = 0; i < 4; i++) {
        const int bb = warp + 16 * i;
        const float* src = g_lin + (size_t)(b0 + bb) * NOUT;
        float* base = reinterpret_cast<float*>(k4_s2) + (bb & 1);
        const int pr = bb >> 1;
        for (int ch = lane; ch < NOUT; ch += 32)
            base[(ch * K4_P + pr) * 2] = src[ch];
    }
    __syncthreads();

    const unsigned long long* s_u64 =
        reinterpret_cast<const unsigned long long*>(k4_s2) + lane;
    unsigned long long c01;
    asm("mov.b64 %0, {%1, %1};" : "=l"(c01) : "f"(0.1f));

#define K4_STEP(ACC, PR)                                                      \
    {                                                                         \
        unsigned long long av = s_u64[((PR).x & 1023) * K4_P];                \
        unsigned long long bv = s_u64[(((PR).x >> 10) & 1023) * K4_P];        \
        const float pf = __uint_as_float((PR).y);                             \
        unsigned long long pp, t;                                             \
        asm("mov.b64 %0, {%1, %1};" : "=l"(pp) : "f"(pf));                    \
        asm("mul.rn.f32x2 %0, %1, %2;" : "=l"(t) : "l"(av), "l"(bv));         \
        asm("fma.rn.f32x2 %0, %1, %2, %0;" : "+l"(ACC) : "l"(t), "l"(pp));    \
    }

#pragma unroll 2
    for (int i = 0; i < 20; i++) {
        const int row = half * 320 + warp + 16 * i;
        const int ks = g_row_start[row];
        const int ke = g_row_start[row + 1];
        unsigned long long a0 = 0ull, a1 = 0ull, a2c = 0ull, a3 = 0ull;
        int k = ks;
        for (; k + 3 < ke; k += 4) {
            const uint2 p0 = g_pair[k + 0];
            const uint2 p1 = g_pair[k + 1];
            const uint2 p2 = g_pair[k + 2];
            const uint2 p3 = g_pair[k + 3];
            K4_STEP(a0, p0)
            K4_STEP(a1, p1)
            K4_STEP(a2c, p2)
            K4_STEP(a3, p3)
        }
        for (; k < ke; k++) {
            const uint2 p0 = g_pair[k];
            K4_STEP(a0, p0)
        }
        unsigned long long acc;
        asm("add.rn.f32x2 %0, %1, %2;" : "=l"(acc) : "l"(a0), "l"(a1));
        asm("add.rn.f32x2 %0, %1, %2;" : "+l"(acc) : "l"(acc), "l"(a2c));
        asm("add.rn.f32x2 %0, %1, %2;" : "+l"(acc) : "l"(acc), "l"(a3));

        unsigned long long linv = s_u64[row * K4_P];
        unsigned long long pv;
        asm("mul.rn.f32x2 %0, %1, %2;" : "=l"(pv) : "l"(acc), "l"(c01));
        asm("add.rn.f32x2 %0, %1, %2;" : "+l"(pv) : "l"(pv), "l"(linv));
        *reinterpret_cast<unsigned long long*>(
            g_pre + (size_t)row * BATCH + b0 + 2 * lane) = pv;
    }
}

// ---------------------------------------------------------------------------
// K4b: gated nonlinearity from transposed preact (FROZEN, ~6us)
// ---------------------------------------------------------------------------
__global__ __launch_bounds__(256) void k4b_gate(
    const int* __restrict__ gate_idx, float* __restrict__ out) {
    __shared__ float s_t[32][257];
    const int tid = threadIdx.x;
    const int b0 = blockIdx.x * 256;
    const int j0 = blockIdx.y * 32;

#pragma unroll 4
    for (int jj = 0; jj < 32; jj++) {
        const int j = j0 + jj;
        const int gi = gate_idx[j];
        const float v = g_pre[(size_t)j * BATCH + b0 + tid];
        const float g = g_pre[(size_t)gi * BATCH + b0 + tid];
        s_t[jj][tid] = v / (1.0f + __expf(-g));
    }
    __syncthreads();

    float* dst = out + (size_t)(b0 + tid) * NREP + j0;
#pragma unroll
    for (int q = 0; q < 8; q++) {
        float4 v = make_float4(s_t[q * 4 + 0][tid], s_t[q * 4 + 1][tid],
                               s_t[q * 4 + 2][tid], s_t[q * 4 + 3][tid]);
        *reinterpret_cast<float4*>(dst + q * 4) = v;
    }
}

// ---------------------------------------------------------------------------
// Launch
// ---------------------------------------------------------------------------
extern "C" void kernel_launch(void* const* d_in, const int* in_sizes, int n_in,
                              void* d_out, int out_size) {
    const float* x        = (const float*)d_in[0];
    const float* W_weight = (const float*)d_in[1];
    const float* b        = (const float*)d_in[2];
    const float* Qw       = (const float*)d_in[3];
    const float* Qb       = (const float*)d_in[4];
    const float* bi_p     = (const float*)d_in[5];
    const int*   bi_src   = (const int*)d_in[6];
    const int*   bi_row   = (const int*)d_in[7];
    const int*   bi_col   = (const int*)d_in[8];
    const int*   gate_idx = (const int*)d_in[9];
    float* out = (float*)d_out;

    static int smem_set = 0;
    const int k4_smem_bytes = NOUT * K4_P * sizeof(float2);  // 168,960
    if (!smem_set) {
        cudaFuncSetAttribute(k4a_bilinear,
                             cudaFuncAttributeMaxDynamicSharedMemorySize,
                             k4_smem_bytes);
        smem_set = 1;
    }

    kz<<<1, 512>>>();
    k1_qwt<<<1312, 512>>>(Qw, W_weight, x);   // 1280 GEMV + 32 x-split blocks
    k2_wp<<<2562, 256>>>(Qw, bi_src, bi_row, bi_col, bi_p, Qb, b);
    k3_mma<<<dim3(NOUT / 64, BATCH / 128), 256>>>();   // launch #4 -> profiled
    k4a_bilinear<<<128, 512, k4_smem_bytes>>>();
    k4b_gate<<<dim3(BATCH / 256, NREP / 32), 256>>>(gate_idx, out);
}